// round 3
// baseline (speedup 1.0000x reference)
#include <cuda_runtime.h>
#include <math.h>

#define BB 64
#define TT 2048
#define II 64
#define HH 128
#define OO 64
#define GG 384   // 3*H

// Scratch for x_proj [B, T, 3H] + 2 steps of padding (distance-2 prefetch
// reads up to t+2 unconditionally). __device__ global (no cudaMalloc allowed).
__device__ float g_xproj[(size_t)BB * TT * GG + 2 * GG];

typedef unsigned long long ull;

// Packed fp32x2 ops (Blackwell): elementwise on 2 floats.
__device__ __forceinline__ ull ffma2(ull a, ull b, ull c) {
    ull d;
    asm("fma.rn.f32x2 %0, %1, %2, %3;" : "=l"(d) : "l"(a), "l"(b), "l"(c));
    return d;
}
__device__ __forceinline__ ull fadd2(ull a, ull b) {
    ull d;
    asm("add.rn.f32x2 %0, %1, %2;" : "=l"(d) : "l"(a), "l"(b));
    return d;
}
__device__ __forceinline__ ull pack2(float lo, float hi) {
    ull d;
    asm("mov.b64 %0, {%1, %2};" : "=l"(d) : "f"(lo), "f"(hi));
    return d;
}
__device__ __forceinline__ float red2(ull a) {
    float x, y;
    asm("mov.b64 {%0,%1}, %2;" : "=f"(x), "=f"(y) : "l"(a));
    return x + y;
}

__device__ __forceinline__ float sigmf(float x) {
    return 1.0f / (1.0f + __expf(-x));
}
// Numerically safe tanh via exp of negative magnitude (no overflow/NaN).
__device__ __forceinline__ float tanh_f(float x) {
    float e = __expf(-2.0f * fabsf(x));
    float r = (1.0f - e) / (1.0f + e);
    return copysignf(r, x);
}

// ---------------------------------------------------------------------------
// Kernel A: x_proj[b,t,g] = dot(x[b,t,:], W_ih[g,:]) + b_ih[g]
// Block = 64 rows x 384 cols; thread = col, W row in regs. 2 rows in flight
// with 2 accumulators each (4 independent FMA chains of depth 8).
// ---------------------------------------------------------------------------
__global__ void __launch_bounds__(384, 1) xproj_kernel(
    const float* __restrict__ x, const float* __restrict__ W_ih,
    const float* __restrict__ b_ih)
{
    __shared__ __align__(16) float xs[64 * II];  // 16 KB, contiguous tile
    int tid = threadIdx.x;
    size_t row0 = (size_t)blockIdx.x * 64;

    for (int idx = tid; idx < 64 * II; idx += 384)
        xs[idx] = x[row0 * II + idx];

    ull w2[II / 2];
    {
        const ulonglong2* wp = (const ulonglong2*)(W_ih + (size_t)tid * II);
#pragma unroll
        for (int i = 0; i < II / 4; i++) {
            ulonglong2 v = wp[i];
            w2[2 * i] = v.x; w2[2 * i + 1] = v.y;
        }
    }
    float bias = b_ih[tid];
    __syncthreads();

    float* dst = g_xproj + row0 * GG + tid;
#pragma unroll 1
    for (int r = 0; r < 64; r += 2) {
        const ulonglong2* xpa = (const ulonglong2*)(xs + r * II);
        const ulonglong2* xpb = (const ulonglong2*)(xs + (r + 1) * II);
        ull a0 = pack2(bias, 0.0f), a1 = 0ULL;   // row r
        ull b0 = pack2(bias, 0.0f), b1 = 0ULL;   // row r+1
#pragma unroll
        for (int i = 0; i < II / 4; i++) {
            ulonglong2 va = xpa[i];  // broadcast LDS.128
            ulonglong2 vb = xpb[i];
            a0 = ffma2(w2[2 * i], va.x, a0);
            a1 = ffma2(w2[2 * i + 1], va.y, a1);
            b0 = ffma2(w2[2 * i], vb.x, b0);
            b1 = ffma2(w2[2 * i + 1], vb.y, b1);
        }
        __stcs(dst + (size_t)r * GG, red2(fadd2(a0, a1)));
        __stcs(dst + (size_t)(r + 1) * GG, red2(fadd2(b0, b1)));
    }
}

// ---------------------------------------------------------------------------
// Kernel B: GRU recurrence. One CTA per batch element, persistent over T.
// 384 threads: thread t owns row t of W_hh (128 weights in registers).
// h in SMEM (broadcast LDS.128). 4 accumulator chains of depth 16.
// x_proj streamed with distance-2 register prefetch into a double buffer.
// ---------------------------------------------------------------------------
__global__ void __launch_bounds__(384, 1) gru_kernel(
    const float* __restrict__ W_hh, const float* __restrict__ b_hh,
    float* __restrict__ latents)
{
    __shared__ __align__(16) float h_s[HH];
    __shared__ float hg_s[GG];
    __shared__ float xg_s[2][GG];

    int tid = threadIdx.x;
    int b = blockIdx.x;

    // W_hh row in registers, packed as 64 f32x2 pairs (128 regs).
    ull w2[HH / 2];
    {
        const ulonglong2* wp = (const ulonglong2*)(W_hh + (size_t)tid * HH);
#pragma unroll
        for (int i = 0; i < HH / 4; i++) {
            ulonglong2 v = wp[i];
            w2[2 * i] = v.x; w2[2 * i + 1] = v.y;
        }
    }
    float bias = b_hh[tid];

    const float* xp = g_xproj + (size_t)b * TT * GG + tid;
    float* lat = latents + (size_t)b * TT * HH + tid;

    if (tid < HH) h_s[tid] = 0.0f;
    xg_s[0][tid] = xp[0];            // x for t=0
    float xnA = xp[GG];              // x for t=1 (pending)
    const float* xp2 = xp + 2 * GG;  // points at t+2
    __syncthreads();

#pragma unroll 1
    for (int t = 0; t < TT; t++) {
        int cur = t & 1;
        // Prefetch x for step t+2 (unconditional: array padded by 2*GG).
        float xnB = xp2[0];
        xp2 += GG;

        // hg[row] = dot(W_hh[row,:], h) + b_hh[row]  (4 chains of 16)
        ull a0 = pack2(bias, 0.0f), a1 = 0ULL, a2 = 0ULL, a3 = 0ULL;
        const ulonglong2* hp = (const ulonglong2*)h_s;
#pragma unroll
        for (int i = 0; i < HH / 8; i++) {
            ulonglong2 v0 = hp[2 * i];      // broadcast LDS.128
            ulonglong2 v1 = hp[2 * i + 1];
            a0 = ffma2(w2[4 * i], v0.x, a0);
            a1 = ffma2(w2[4 * i + 1], v0.y, a1);
            a2 = ffma2(w2[4 * i + 2], v1.x, a2);
            a3 = ffma2(w2[4 * i + 3], v1.y, a3);
        }
        hg_s[tid] = red2(fadd2(fadd2(a0, a1), fadd2(a2, a3)));
        __syncthreads();

        if (tid < HH) {
            float xr = xg_s[cur][tid];
            float xz = xg_s[cur][HH + tid];
            float xn = xg_s[cur][2 * HH + tid];
            float hr = hg_s[tid];
            float hz = hg_s[HH + tid];
            float hn = hg_s[2 * HH + tid];
            float rg = sigmf(xr + hr);
            float zg = sigmf(xz + hz);
            float ng = tanh_f(xn + rg * hn);
            float hnew = (1.0f - zg) * ng + zg * h_s[tid];
            h_s[tid] = hnew;
            __stcs(lat, hnew);
        }
        lat += HH;
        xg_s[cur ^ 1][tid] = xnA;  // fill next buffer (after sync #1: safe)
        xnA = xnB;
        __syncthreads();
    }
}

// ---------------------------------------------------------------------------
// Kernel C: output[b,t,o] = dot(latents[b,t,:], W_out[o,:]) + b_out[o]
// Block = 64 rows x 64 cols; 256 threads = (o, row-quarter). W_out row in
// regs; 2 rows in flight x 2 accums (4 chains of 16).
// ---------------------------------------------------------------------------
__global__ void __launch_bounds__(256, 1) out_kernel(
    const float* __restrict__ latents, const float* __restrict__ W_out,
    const float* __restrict__ b_out, float* __restrict__ out)
{
    __shared__ __align__(16) float lt[64 * HH];  // 32 KB
    int tid = threadIdx.x;
    size_t row0 = (size_t)blockIdx.x * 64;

    {
        const float4* src = (const float4*)(latents + row0 * HH);
        float4* dst = (float4*)lt;
        for (int idx = tid; idx < 64 * HH / 4; idx += 256) dst[idx] = src[idx];
    }

    int o = tid & 63;
    int q = tid >> 6;  // 0..3 -> 16 rows each

    ull w2[HH / 2];
    {
        const ulonglong2* wp = (const ulonglong2*)(W_out + (size_t)o * HH);
#pragma unroll
        for (int i = 0; i < HH / 4; i++) {
            ulonglong2 v = wp[i];
            w2[2 * i] = v.x; w2[2 * i + 1] = v.y;
        }
    }
    float bias = b_out[o];
    __syncthreads();

#pragma unroll 1
    for (int j = 0; j < 16; j += 2) {
        int r = q * 16 + j;
        const ulonglong2* lpa = (const ulonglong2*)(lt + r * HH);
        const ulonglong2* lpb = (const ulonglong2*)(lt + (r + 1) * HH);
        ull a0 = pack2(bias, 0.0f), a1 = 0ULL;
        ull b0 = pack2(bias, 0.0f), b1 = 0ULL;
#pragma unroll
        for (int i = 0; i < HH / 4; i++) {
            ulonglong2 va = lpa[i];  // broadcast LDS.128
            ulonglong2 vb = lpb[i];
            a0 = ffma2(w2[2 * i], va.x, a0);
            a1 = ffma2(w2[2 * i + 1], va.y, a1);
            b0 = ffma2(w2[2 * i], vb.x, b0);
            b1 = ffma2(w2[2 * i + 1], vb.y, b1);
        }
        __stcs(out + (row0 + r) * OO + o, red2(fadd2(a0, a1)));
        __stcs(out + (row0 + r + 1) * OO + o, red2(fadd2(b0, b1)));
    }
}

// ---------------------------------------------------------------------------
extern "C" void kernel_launch(void* const* d_in, const int* in_sizes, int n_in,
                              void* d_out, int out_size) {
    const float* x     = (const float*)d_in[0];
    const float* W_ih  = (const float*)d_in[1];
    const float* W_hh  = (const float*)d_in[2];
    const float* b_ih  = (const float*)d_in[3];
    const float* b_hh  = (const float*)d_in[4];
    const float* W_out = (const float*)d_in[5];
    const float* b_out = (const float*)d_in[6];

    float* out = (float*)d_out;                        // [B,T,O] first
    float* latents = out + (size_t)BB * TT * OO;       // then [B,T,H]

    xproj_kernel<<<(BB * TT) / 64, 384>>>(x, W_ih, b_ih);
    gru_kernel<<<BB, 384>>>(W_hh, b_hh, latents);
    out_kernel<<<(BB * TT) / 64, 256>>>(latents, W_out, b_out, out);
}

// round 4
// speedup vs baseline: 1.1117x; 1.1117x over previous
#include <cuda_runtime.h>
#include <math.h>

#define BB 64
#define TT 2048
#define II 64
#define HH 128
#define OO 64
#define GG 384   // 3*H

// Scratch for x_proj [B, T, 3H] + 2 steps of padding (distance-2 prefetch
// reads up to t+2 unconditionally). __device__ global (no cudaMalloc allowed).
__device__ float g_xproj[(size_t)BB * TT * GG + 2 * GG];

typedef unsigned long long ull;

// Packed fp32x2 ops (Blackwell): elementwise on 2 floats.
__device__ __forceinline__ ull ffma2(ull a, ull b, ull c) {
    ull d;
    asm("fma.rn.f32x2 %0, %1, %2, %3;" : "=l"(d) : "l"(a), "l"(b), "l"(c));
    return d;
}
__device__ __forceinline__ ull fadd2(ull a, ull b) {
    ull d;
    asm("add.rn.f32x2 %0, %1, %2;" : "=l"(d) : "l"(a), "l"(b));
    return d;
}
__device__ __forceinline__ ull pack2(float lo, float hi) {
    ull d;
    asm("mov.b64 %0, {%1, %2};" : "=l"(d) : "f"(lo), "f"(hi));
    return d;
}
__device__ __forceinline__ float red2(ull a) {
    float x, y;
    asm("mov.b64 {%0,%1}, %2;" : "=f"(x), "=f"(y) : "l"(a));
    return x + y;
}

// Single-instruction MUFU.TANH (sm_75+). ~1e-5 abs error; GRU recurrence is a
// contraction so the error does not accumulate beyond ~1e-5 steady-state.
__device__ __forceinline__ float tanhap(float x) {
    float y;
    asm("tanh.approx.f32 %0, %1;" : "=f"(y) : "f"(x));
    return y;
}
__device__ __forceinline__ float sigmap(float x) {
    return 0.5f + 0.5f * tanhap(0.5f * x);
}

// ---------------------------------------------------------------------------
// Kernel A: x_proj[b,t,g] = dot(x[b,t,:], W_ih[g,:]) + b_ih[g]
// Grid (2048, 3): block = 64 rows x 128 cols (one gate). 128 threads, one col
// each; W_ih row in regs; x tile in SMEM (broadcast LDS.128). Small CTAs ->
// ~5 CTAs/SM to fix the measured occupancy/issue ceiling.
// ---------------------------------------------------------------------------
__global__ void __launch_bounds__(128) xproj_kernel(
    const float* __restrict__ x, const float* __restrict__ W_ih,
    const float* __restrict__ b_ih)
{
    __shared__ __align__(16) float xs[64 * II];  // 16 KB, contiguous tile
    int tid = threadIdx.x;
    size_t row0 = (size_t)blockIdx.x * 64;
    int col = blockIdx.y * HH + tid;   // output gate column = W_ih row

    {
        const float4* src = (const float4*)(x + row0 * II);
        float4* dst4 = (float4*)xs;
        for (int idx = tid; idx < 64 * II / 4; idx += 128) dst4[idx] = src[idx];
    }

    ull w2[II / 2];
    {
        const ulonglong2* wp = (const ulonglong2*)(W_ih + (size_t)col * II);
#pragma unroll
        for (int i = 0; i < II / 4; i++) {
            ulonglong2 v = wp[i];
            w2[2 * i] = v.x; w2[2 * i + 1] = v.y;
        }
    }
    float bias = b_ih[col];
    __syncthreads();

    float* dst = g_xproj + row0 * GG + col;
#pragma unroll 1
    for (int r = 0; r < 64; r += 2) {
        const ulonglong2* xpa = (const ulonglong2*)(xs + r * II);
        const ulonglong2* xpb = (const ulonglong2*)(xs + (r + 1) * II);
        ull a0 = pack2(bias, 0.0f), a1 = 0ULL;   // row r
        ull b0 = pack2(bias, 0.0f), b1 = 0ULL;   // row r+1
#pragma unroll
        for (int i = 0; i < II / 4; i++) {
            ulonglong2 va = xpa[i];  // broadcast LDS.128
            ulonglong2 vb = xpb[i];
            a0 = ffma2(w2[2 * i], va.x, a0);
            a1 = ffma2(w2[2 * i + 1], va.y, a1);
            b0 = ffma2(w2[2 * i], vb.x, b0);
            b1 = ffma2(w2[2 * i + 1], vb.y, b1);
        }
        __stcs(dst + (size_t)r * GG, red2(fadd2(a0, a1)));
        __stcs(dst + (size_t)(r + 1) * GG, red2(fadd2(b0, b1)));
    }
}

// ---------------------------------------------------------------------------
// Kernel B: GRU recurrence. One CTA per batch element, persistent over T.
// 384 threads: thread t owns row t of W_hh (128 weights in registers).
// h in SMEM (broadcast LDS.128). 4 accumulator chains of depth 16.
// Epilogue (tid<128): gate x-values live in REGISTERS, prefetched at
// distance 2 (no xg SMEM staging). tanh.approx for all activations.
// ---------------------------------------------------------------------------
__global__ void __launch_bounds__(384, 1) gru_kernel(
    const float* __restrict__ W_hh, const float* __restrict__ b_hh,
    float* __restrict__ latents)
{
    __shared__ __align__(16) float h_s[HH];
    __shared__ float hg_s[GG];

    int tid = threadIdx.x;
    int b = blockIdx.x;

    // W_hh row in registers, packed as 64 f32x2 pairs (128 regs).
    ull w2[HH / 2];
    {
        const ulonglong2* wp = (const ulonglong2*)(W_hh + (size_t)tid * HH);
#pragma unroll
        for (int i = 0; i < HH / 4; i++) {
            ulonglong2 v = wp[i];
            w2[2 * i] = v.x; w2[2 * i + 1] = v.y;
        }
    }
    float bias = b_hh[tid];

    const float* xbase = g_xproj + (size_t)b * TT * GG;
    float* lat = latents + (size_t)b * TT * HH + tid;

    // Epilogue-thread register pipeline for gate x-values: step t (0-regs),
    // step t+1 (1-regs); prefetch t+2 each iteration.
    float xr0 = 0, xz0 = 0, xn0 = 0, xr1 = 0, xz1 = 0, xn1 = 0;
    if (tid < HH) {
        h_s[tid] = 0.0f;
        xr0 = xbase[tid];           xz0 = xbase[HH + tid];      xn0 = xbase[2 * HH + tid];
        xr1 = xbase[GG + tid];      xz1 = xbase[GG + HH + tid]; xn1 = xbase[GG + 2 * HH + tid];
    }
    const float* xq = xbase + 2 * GG;  // points at step t+2
    __syncthreads();

#pragma unroll 1
    for (int t = 0; t < TT; t++) {
        // Prefetch x-gates for step t+2 (padded region makes this safe).
        float pr = 0, pz = 0, pn = 0;
        if (tid < HH) {
            pr = xq[tid]; pz = xq[HH + tid]; pn = xq[2 * HH + tid];
        }
        xq += GG;

        // hg[row] = dot(W_hh[row,:], h) + b_hh[row]  (4 chains of 16)
        ull a0 = pack2(bias, 0.0f), a1 = 0ULL, a2 = 0ULL, a3 = 0ULL;
        const ulonglong2* hp = (const ulonglong2*)h_s;
#pragma unroll
        for (int i = 0; i < HH / 8; i++) {
            ulonglong2 v0 = hp[2 * i];      // broadcast LDS.128
            ulonglong2 v1 = hp[2 * i + 1];
            a0 = ffma2(w2[4 * i], v0.x, a0);
            a1 = ffma2(w2[4 * i + 1], v0.y, a1);
            a2 = ffma2(w2[4 * i + 2], v1.x, a2);
            a3 = ffma2(w2[4 * i + 3], v1.y, a3);
        }
        hg_s[tid] = red2(fadd2(fadd2(a0, a1), fadd2(a2, a3)));
        __syncthreads();

        if (tid < HH) {
            float rg = sigmap(xr0 + hg_s[tid]);
            float zg = sigmap(xz0 + hg_s[HH + tid]);
            float ng = tanhap(xn0 + rg * hg_s[2 * HH + tid]);
            float hnew = ng + zg * (h_s[tid] - ng);
            h_s[tid] = hnew;
            __stcs(lat, hnew);
        }
        lat += HH;
        xr0 = xr1; xz0 = xz1; xn0 = xn1;
        xr1 = pr;  xz1 = pz;  xn1 = pn;
        __syncthreads();
    }
}

// ---------------------------------------------------------------------------
// Kernel C: output[b,t,o] = dot(latents[b,t,:], W_out[o,:]) + b_out[o]
// Block = 64 rows x 64 cols; 256 threads = (o, row-quarter). W_out row in
// regs; 2 rows in flight x 2 accums.
// ---------------------------------------------------------------------------
__global__ void __launch_bounds__(256) out_kernel(
    const float* __restrict__ latents, const float* __restrict__ W_out,
    const float* __restrict__ b_out, float* __restrict__ out)
{
    __shared__ __align__(16) float lt[64 * HH];  // 32 KB
    int tid = threadIdx.x;
    size_t row0 = (size_t)blockIdx.x * 64;

    {
        const float4* src = (const float4*)(latents + row0 * HH);
        float4* dst = (float4*)lt;
        for (int idx = tid; idx < 64 * HH / 4; idx += 256) dst[idx] = src[idx];
    }

    int o = tid & 63;
    int q = tid >> 6;  // 0..3 -> 16 rows each

    ull w2[HH / 2];
    {
        const ulonglong2* wp = (const ulonglong2*)(W_out + (size_t)o * HH);
#pragma unroll
        for (int i = 0; i < HH / 4; i++) {
            ulonglong2 v = wp[i];
            w2[2 * i] = v.x; w2[2 * i + 1] = v.y;
        }
    }
    float bias = b_out[o];
    __syncthreads();

#pragma unroll 1
    for (int j = 0; j < 16; j += 2) {
        int r = q * 16 + j;
        const ulonglong2* lpa = (const ulonglong2*)(lt + r * HH);
        const ulonglong2* lpb = (const ulonglong2*)(lt + (r + 1) * HH);
        ull a0 = pack2(bias, 0.0f), a1 = 0ULL;
        ull b0 = pack2(bias, 0.0f), b1 = 0ULL;
#pragma unroll
        for (int i = 0; i < HH / 4; i++) {
            ulonglong2 va = lpa[i];  // broadcast LDS.128
            ulonglong2 vb = lpb[i];
            a0 = ffma2(w2[2 * i], va.x, a0);
            a1 = ffma2(w2[2 * i + 1], va.y, a1);
            b0 = ffma2(w2[2 * i], vb.x, b0);
            b1 = ffma2(w2[2 * i + 1], vb.y, b1);
        }
        __stcs(out + (row0 + r) * OO + o, red2(fadd2(a0, a1)));
        __stcs(out + (row0 + r + 1) * OO + o, red2(fadd2(b0, b1)));
    }
}

// ---------------------------------------------------------------------------
extern "C" void kernel_launch(void* const* d_in, const int* in_sizes, int n_in,
                              void* d_out, int out_size) {
    const float* x     = (const float*)d_in[0];
    const float* W_ih  = (const float*)d_in[1];
    const float* W_hh  = (const float*)d_in[2];
    const float* b_ih  = (const float*)d_in[3];
    const float* b_hh  = (const float*)d_in[4];
    const float* W_out = (const float*)d_in[5];
    const float* b_out = (const float*)d_in[6];

    float* out = (float*)d_out;                        // [B,T,O] first
    float* latents = out + (size_t)BB * TT * OO;       // then [B,T,H]

    dim3 xg((BB * TT) / 64, 3);
    xproj_kernel<<<xg, 128>>>(x, W_ih, b_ih);
    gru_kernel<<<BB, 384>>>(W_hh, b_hh, latents);
    out_kernel<<<(BB * TT) / 64, 256>>>(latents, W_out, b_out, out);
}